// round 2
// baseline (speedup 1.0000x reference)
#include <cuda_runtime.h>
#include <cuda_bf16.h>
#include <cstdint>

// BagOfWords: inputs [B=1024, S=512] int32 token ids in [0, 50257).
// Output: counts [B, 50256] float32 (token id 0 dropped, out[b, t-1] = count of t).
//
// Structure:
//   1) cudaMemsetAsync zero-fill of the 206 MB output (HBM-write-bound, the
//      dominant cost; driver memset hits the LTS/DRAM ceiling).
//   2) scatter kernel: one thread per token, atomicAdd (no return -> REDG).

static constexpr int VOCAB_OUT = 50256;  // 50257 - 1 (token 0 dropped)

__global__ void bow_scatter_kernel(const int* __restrict__ tokens,
                                   float* __restrict__ out,
                                   int total, int seq_len) {
    int i = blockIdx.x * blockDim.x + threadIdx.x;
    if (i >= total) return;
    int t = tokens[i];
    if (t > 0) {
        int b = i / seq_len;
        atomicAdd(out + (size_t)b * VOCAB_OUT + (t - 1), 1.0f);
    }
}

extern "C" void kernel_launch(void* const* d_in, const int* in_sizes, int n_in,
                              void* d_out, int out_size) {
    const int* tokens = (const int*)d_in[0];
    float* out = (float*)d_out;

    const int total = in_sizes[0];             // B * S = 524288
    const int B = out_size / VOCAB_OUT;        // 1024
    const int S = total / B;                   // 512

    // Zero the output histogram (dominant cost: ~206 MB of HBM writes).
    cudaMemsetAsync(d_out, 0, (size_t)out_size * sizeof(float), 0);

    // Scatter-add counts.
    const int threads = 256;
    const int blocks = (total + threads - 1) / threads;
    bow_scatter_kernel<<<blocks, threads>>>(tokens, out, total, S);
}

// round 3
// speedup vs baseline: 1.2336x; 1.2336x over previous
#include <cuda_runtime.h>
#include <cuda_bf16.h>
#include <cstdint>

// BagOfWords: inputs [B=1024, S=512] int32 token ids in [0, 50257).
// Output: counts [B, 50256] float32 (token id 0 dropped: out[b, t-1] = count of t).
//
// Single fused kernel, one CTA per batch row:
//   1) zero a packed-u16 smem histogram (50258 counts = 100.5 KB -> 2 CTAs/SM)
//   2) smem atomicAdd per token (packed: +1 in low/high u16 half of a u32 word;
//      max count 512 << 65536 so no carry into the neighbor)
//   3) coalesced float4 writeout of the row (output written exactly ONCE -
//      no global memset pass, no global atomics)

static constexpr int VOCAB_OUT = 50256;                 // 50257 - 1 (token 0 dropped)
static constexpr int N_TOKENS  = VOCAB_OUT + 1;         // 50257
static constexpr int N_WORDS   = (N_TOKENS + 1) / 2;    // 25129 packed u32 words
static constexpr int N_WORDS_P = (N_WORDS + 3) & ~3;    // 25132, padded for uint4 zeroing
static constexpr int SMEM_BYTES = N_WORDS_P * 4;        // 100528 B
static constexpr int THREADS   = 1024;

__global__ __launch_bounds__(THREADS)
void bow_fused_kernel(const int* __restrict__ tokens,
                      float* __restrict__ out,
                      int seq_len) {
    extern __shared__ uint32_t hist[];   // packed u16 counts

    const int b   = blockIdx.x;
    const int tid = threadIdx.x;

    // 1) zero smem histogram (uint4 stores)
    uint4* h4 = reinterpret_cast<uint4*>(hist);
    #pragma unroll
    for (int i = tid; i < N_WORDS_P / 4; i += THREADS)
        h4[i] = make_uint4(0u, 0u, 0u, 0u);
    __syncthreads();

    // 2) accumulate tokens for this row (packed u16 smem atomics)
    const int* row = tokens + (size_t)b * seq_len;
    for (int i = tid; i < seq_len; i += THREADS) {
        int t = row[i];
        atomicAdd(&hist[t >> 1], 1u << ((t & 1) * 16));
    }
    __syncthreads();

    // 3) coalesced writeout: out[b][o] = count(token o+1), float4 per thread/iter
    const uint16_t* h16 = reinterpret_cast<const uint16_t*>(hist);
    float4* out4 = reinterpret_cast<float4*>(out + (size_t)b * VOCAB_OUT);
    const int n4 = VOCAB_OUT / 4;   // 12564 (VOCAB_OUT % 4 == 0)
    for (int i = tid; i < n4; i += THREADS) {
        int o = i * 4;
        float4 v;
        v.x = (float)h16[o + 1];
        v.y = (float)h16[o + 2];
        v.z = (float)h16[o + 3];
        v.w = (float)h16[o + 4];
        out4[i] = v;
    }
}

extern "C" void kernel_launch(void* const* d_in, const int* in_sizes, int n_in,
                              void* d_out, int out_size) {
    const int* tokens = (const int*)d_in[0];
    float* out = (float*)d_out;

    const int total = in_sizes[0];          // B * S
    const int B = out_size / VOCAB_OUT;     // 1024
    const int S = total / B;                // 512

    cudaFuncSetAttribute(bow_fused_kernel,
                         cudaFuncAttributeMaxDynamicSharedMemorySize, SMEM_BYTES);

    bow_fused_kernel<<<B, THREADS, SMEM_BYTES>>>(tokens, out, S);
}